// round 1
// baseline (speedup 1.0000x reference)
#include <cuda_runtime.h>
#include <cuda_bf16.h>

#define H_IMG 224
#define W_IMG 224
#define NPIX (H_IMG * W_IMG)          // 50176
#define BATCH 32
#define KKP 64
#define PATCH 16
#define NCLASS 1000
#define NPATCH (BATCH * KKP)          // 2048
#define FEAT 2048                      // 8*16*16
#define FC1OUT 64
#define FC2IN (KKP * FC1OUT)          // 4096

// -------------------- device scratch (no allocation allowed) --------------------
__device__ float g_R[BATCH * NPIX];                 // 6.4 MB harris response (masked)
__device__ int   g_kp[BATCH * KKP];                 // flat pixel indices, rank-ordered
__device__ float g_H1[NPATCH * FEAT];               // 16 MB conv features
__device__ float g_Cpart[4 * NPATCH * FC1OUT];      // 2 MB split-K partials
__device__ float g_H2[NPATCH * FC1OUT];             // 512 KB relu(fc1)

// ==================== 1. Harris response ====================
__global__ void __launch_bounds__(1024) harris_kernel(const float* __restrict__ x) {
    __shared__ float g[36][37];
    __shared__ float dxs[34][35];
    __shared__ float dys[34][35];

    const int b  = blockIdx.z;
    const int ox0 = blockIdx.x * 32, oy0 = blockIdx.y * 32;
    const int tid = threadIdx.y * 32 + threadIdx.x;
    const float* xb = x + (size_t)b * 3 * NPIX;

    for (int i = tid; i < 36 * 36; i += 1024) {
        int r = i / 36, c = i % 36;
        int yy = oy0 - 2 + r, xx = ox0 - 2 + c;
        float v = 0.0f;
        if (yy >= 0 && yy < H_IMG && xx >= 0 && xx < W_IMG) {
            int off = yy * W_IMG + xx;
            v = (xb[off] + xb[NPIX + off] + xb[2 * NPIX + off]) / 3.0f;
        }
        g[r][c] = v;
    }
    __syncthreads();

    for (int i = tid; i < 34 * 34; i += 1024) {
        int r = i / 34, c = i % 34;
        float lft = g[r][c]     + g[r + 1][c]     + g[r + 2][c];
        float rgt = g[r][c + 2] + g[r + 1][c + 2] + g[r + 2][c + 2];
        float top = g[r][c]     + g[r][c + 1]     + g[r][c + 2];
        float bot = g[r + 2][c] + g[r + 2][c + 1] + g[r + 2][c + 2];
        dxs[r][c] = rgt - lft;
        dys[r][c] = bot - top;
    }
    __syncthreads();

    const int ty = threadIdx.y, tx = threadIdx.x;
    const int oy = oy0 + ty, ox = ox0 + tx;

    const float GW[3][3] = {{0.0625f, 0.125f, 0.0625f},
                            {0.125f,  0.25f,  0.125f},
                            {0.0625f, 0.125f, 0.0625f}};
    float sxx = 0.f, syy = 0.f, sxy = 0.f;
#pragma unroll
    for (int u = 0; u < 3; u++)
#pragma unroll
        for (int v = 0; v < 3; v++) {
            float w = GW[u][v];
            float a = dxs[ty + u][tx + v];
            float d = dys[ty + u][tx + v];
            sxx += w * (a * a);
            syy += w * (d * d);
            sxy += w * (a * d);
        }
    float tr = sxx + syy;
    float R = sxx * syy - sxy * sxy - 0.04f * tr * tr;
    bool inmask = (oy >= PATCH && oy < H_IMG - PATCH && ox >= PATCH && ox < W_IMG - PATCH);
    g_R[(size_t)b * NPIX + oy * W_IMG + ox] = inmask ? R : 0.0f;
}

// ==================== 2. exact top-64 (radix select) ====================
__device__ __forceinline__ unsigned int fkey(float f) {
    unsigned int u = __float_as_uint(f);
    return (u & 0x80000000u) ? ~u : (u | 0x80000000u);
}

__global__ void __launch_bounds__(1024) topk_kernel() {
    const int b = blockIdx.x;
    const float* R = g_R + (size_t)b * NPIX;
    const int tid = threadIdx.x;

    __shared__ unsigned int hist[256];
    __shared__ unsigned int sh_prefix;
    __shared__ int sh_kneed;
    __shared__ unsigned int sh_keys[64];
    __shared__ unsigned int sh_idx[64];
    __shared__ unsigned long long skeys[64];
    __shared__ int sh_cnt;
    __shared__ int sh_min;

    unsigned int prefix = 0;
    int kneed = KKP;

    for (int level = 0; level < 4; level++) {
        int shift = 24 - 8 * level;
        if (tid < 256) hist[tid] = 0u;
        __syncthreads();
        for (int i = tid; i < NPIX; i += 1024) {
            unsigned int u = fkey(R[i]);
            bool ok = (level == 0) || (((u ^ prefix) >> (shift + 8)) == 0u);
            if (ok) atomicAdd(&hist[(u >> shift) & 0xFFu], 1u);
        }
        __syncthreads();
        if (tid == 0) {
            int cum = 0, d = 255;
            for (; d >= 0; d--) {
                cum += (int)hist[d];
                if (cum >= kneed) break;
            }
            sh_kneed = kneed - (cum - (int)hist[d]);
            sh_prefix = prefix | ((unsigned int)d << shift);
        }
        __syncthreads();
        prefix = sh_prefix;
        kneed = sh_kneed;
        __syncthreads();
    }

    const unsigned int T = prefix;
    const int cGT = KKP - kneed;

    if (tid == 0) sh_cnt = 0;
    __syncthreads();
    for (int i = tid; i < NPIX; i += 1024) {
        unsigned int u = fkey(R[i]);
        if (u > T) {
            int pos = atomicAdd(&sh_cnt, 1);
            if (pos < 64) { sh_keys[pos] = u; sh_idx[pos] = (unsigned int)i; }
        }
    }
    __syncthreads();

    if (tid < 64) {
        skeys[tid] = (tid < cGT)
            ? (((unsigned long long)(~sh_keys[tid]) << 32) | (unsigned long long)sh_idx[tid])
            : 0xFFFFFFFFFFFFFFFFULL;
    }
    __syncthreads();

    // bitonic sort ascending -> (value desc, idx asc)
    for (int ksz = 2; ksz <= 64; ksz <<= 1) {
        for (int j = ksz >> 1; j > 0; j >>= 1) {
            if (tid < 64) {
                int ixj = tid ^ j;
                if (ixj > tid) {
                    bool up = ((tid & ksz) == 0);
                    unsigned long long a = skeys[tid], c = skeys[ixj];
                    if ((a > c) == up) { skeys[tid] = c; skeys[ixj] = a; }
                }
            }
            __syncthreads();
        }
    }

    if (tid < cGT) g_kp[b * KKP + tid] = (int)(skeys[tid] & 0xFFFFFFFFULL);

    // ties (== T): smallest indices first
    int last = -1;
    for (int t = 0; t < kneed; t++) {
        if (tid == 0) sh_min = NPIX;
        __syncthreads();
        for (int i = tid; i < NPIX; i += 1024) {
            if (i > last && fkey(R[i]) == T) atomicMin(&sh_min, i);
        }
        __syncthreads();
        if (tid == 0) g_kp[b * KKP + cGT + t] = sh_min;
        last = sh_min;
        __syncthreads();
    }
}

// ==================== 3. patch extraction + conv3x3 + relu ====================
__global__ void __launch_bounds__(256) patch_conv_kernel(const float* __restrict__ x,
                                                         const float* __restrict__ conv_w,
                                                         const float* __restrict__ conv_b) {
    __shared__ float sp[3][16][16];
    __shared__ float sw[8 * 27];
    __shared__ float sb[8];

    const int p  = blockIdx.x;
    const int b  = p >> 6;
    const int kk = p & 63;
    const int tid = threadIdx.x;

    if (tid < 216) sw[tid] = conv_w[tid];
    else if (tid < 224) sb[tid - 216] = conv_b[tid - 216];

    const int idx = g_kp[b * KKP + kk];
    const float rowf = (float)(idx / W_IMG);
    const float colf = (float)(idx % W_IMG);
    // coords = clip((r/H - .5)*2), coords01 = (coords+1)/2
    float cy = fminf(fmaxf((rowf / 224.0f - 0.5f) * 2.0f, -1.0f), 1.0f);
    float cx = fminf(fmaxf((colf / 224.0f - 0.5f) * 2.0f, -1.0f), 1.0f);
    float y01 = (cy + 1.0f) * 0.5f;
    float x01 = (cx + 1.0f) * 0.5f;

    const float rf = 16.0f / 224.0f;
    const float step = (2.0f * rf) / 15.0f;

    for (int s = tid; s < 768; s += 256) {
        int c = s >> 8;
        int pos = s & 255;
        int i = pos >> 4, j = pos & 15;
        float pgj = (j == 15) ? rf : (-rf + (float)j * step);
        float pgi = (i == 15) ? rf : (-rf + (float)i * step);
        // NOTE: faithful to reference's swapped broadcast: grid_x uses row(y01), grid_y uses col(x01)
        float gxn = (pgj + y01) * 2.0f - 1.0f;
        float gyn = (pgi + x01) * 2.0f - 1.0f;
        float gx = (gxn + 1.0f) * 0.5f * 223.0f;
        float gy = (gyn + 1.0f) * 0.5f * 223.0f;

        float x0f = floorf(gx), y0f = floorf(gy);
        float wx1 = gx - x0f, wx0 = 1.0f - wx1;
        float wy1 = gy - y0f, wy0 = 1.0f - wy1;
        int x0 = (int)x0f, y0 = (int)y0f;
        int x1 = x0 + 1, y1 = y0 + 1;

        const float* img = x + ((size_t)b * 3 + c) * NPIX;
        auto fetch = [&](int xi, int yi) -> float {
            bool v = (xi >= 0 && xi < W_IMG && yi >= 0 && yi < H_IMG);
            int xc = min(max(xi, 0), W_IMG - 1);
            int yc = min(max(yi, 0), H_IMG - 1);
            float val = img[yc * W_IMG + xc];
            return v ? val : 0.0f;
        };
        float out = fetch(x0, y0) * (wx0 * wy0)
                  + fetch(x1, y0) * (wx1 * wy0)
                  + fetch(x0, y1) * (wx0 * wy1)
                  + fetch(x1, y1) * (wx1 * wy1);
        sp[c][i][j] = out;
    }
    __syncthreads();

    const int i = tid >> 4, j = tid & 15;
    float nb[3][3][3];
#pragma unroll
    for (int ci = 0; ci < 3; ci++)
#pragma unroll
        for (int u = 0; u < 3; u++)
#pragma unroll
            for (int v = 0; v < 3; v++) {
                int iy = i + u - 1, ix = j + v - 1;
                nb[ci][u][v] = (iy >= 0 && iy < 16 && ix >= 0 && ix < 16) ? sp[ci][iy][ix] : 0.0f;
            }

#pragma unroll
    for (int co = 0; co < 8; co++) {
        float acc = sb[co];
#pragma unroll
        for (int ci = 0; ci < 3; ci++)
#pragma unroll
            for (int u = 0; u < 3; u++)
#pragma unroll
                for (int v = 0; v < 3; v++)
                    acc += nb[ci][u][v] * sw[co * 27 + ci * 9 + u * 3 + v];
        g_H1[(size_t)p * FEAT + co * 256 + tid] = fmaxf(acc, 0.0f);
    }
}

// ==================== 4. fc1 GEMM (split-K=4, 4x4 register tiles) ====================
__global__ void __launch_bounds__(128) fc1_kernel(const float* __restrict__ fc1_w) {
    __shared__ float As[32][66];
    __shared__ float Bs[64][65];

    const int p0 = blockIdx.x * 32;
    const int k0 = blockIdx.y * 512;
    const int tid = threadIdx.x;
    const int tp = (tid >> 4) * 4;   // patch base 0..28
    const int to = (tid & 15) * 4;   // output base 0..60

    float acc[4][4];
#pragma unroll
    for (int m = 0; m < 4; m++)
#pragma unroll
        for (int n = 0; n < 4; n++) acc[m][n] = 0.0f;

    for (int kc = 0; kc < 512; kc += 64) {
        for (int q = tid; q < 32 * 64; q += 128) {
            int pp = q >> 6, kk = q & 63;
            As[pp][kk] = g_H1[(size_t)(p0 + pp) * FEAT + k0 + kc + kk];
        }
        for (int q = tid; q < 64 * 64; q += 128) {
            int o = q >> 6, kk = q & 63;
            Bs[kk][o] = fc1_w[(size_t)o * FEAT + k0 + kc + kk];
        }
        __syncthreads();
#pragma unroll 8
        for (int kk = 0; kk < 64; kk++) {
            float a0 = As[tp][kk], a1 = As[tp + 1][kk], a2 = As[tp + 2][kk], a3 = As[tp + 3][kk];
            float b0 = Bs[kk][to], b1 = Bs[kk][to + 1], b2 = Bs[kk][to + 2], b3 = Bs[kk][to + 3];
            acc[0][0] += a0 * b0; acc[0][1] += a0 * b1; acc[0][2] += a0 * b2; acc[0][3] += a0 * b3;
            acc[1][0] += a1 * b0; acc[1][1] += a1 * b1; acc[1][2] += a1 * b2; acc[1][3] += a1 * b3;
            acc[2][0] += a2 * b0; acc[2][1] += a2 * b1; acc[2][2] += a2 * b2; acc[2][3] += a2 * b3;
            acc[3][0] += a3 * b0; acc[3][1] += a3 * b1; acc[3][2] += a3 * b2; acc[3][3] += a3 * b3;
        }
        __syncthreads();
    }

    float* Cp = g_Cpart + (size_t)blockIdx.y * NPATCH * FC1OUT;
#pragma unroll
    for (int m = 0; m < 4; m++)
#pragma unroll
        for (int n = 0; n < 4; n++)
            Cp[(size_t)(p0 + tp + m) * FC1OUT + to + n] = acc[m][n];
}

__global__ void __launch_bounds__(256) fc1_finish(const float* __restrict__ fc1_b) {
    int idx = blockIdx.x * 256 + threadIdx.x;   // < 131072
    int o = idx & 63;
    float v = g_Cpart[idx]
            + g_Cpart[NPATCH * FC1OUT + idx]
            + g_Cpart[2 * NPATCH * FC1OUT + idx]
            + g_Cpart[3 * NPATCH * FC1OUT + idx]
            + fc1_b[o];
    g_H2[idx] = fmaxf(v, 0.0f);
}

// ==================== 5. fc2 GEMM ====================
__global__ void __launch_bounds__(256) fc2_kernel(const float* __restrict__ w2,
                                                  const float* __restrict__ b2,
                                                  float* __restrict__ out) {
    __shared__ float sH[32][129];
    __shared__ float sW[8][128];

    const int n0 = blockIdx.x * 8;
    const int tid = threadIdx.x;
    const int warp = tid >> 5, lane = tid & 31;
    const int n = n0 + warp;

    float acc = 0.0f;
    for (int k0 = 0; k0 < FC2IN; k0 += 128) {
        for (int q = tid; q < 32 * 128; q += 256) {
            int bb = q >> 7, kk = q & 127;
            sH[bb][kk] = g_H2[(size_t)bb * FC2IN + k0 + kk];
        }
        for (int q = tid; q < 8 * 128; q += 256) {
            int oo = q >> 7, kk = q & 127;
            sW[oo][kk] = w2[(size_t)(n0 + oo) * FC2IN + k0 + kk];
        }
        __syncthreads();
#pragma unroll 16
        for (int kk = 0; kk < 128; kk++)
            acc += sH[lane][kk] * sW[warp][kk];
        __syncthreads();
    }
    out[lane * NCLASS + n] = acc + b2[n];
}

// ==================== launch ====================
extern "C" void kernel_launch(void* const* d_in, const int* in_sizes, int n_in,
                              void* d_out, int out_size) {
    const float* x      = (const float*)d_in[0];
    const float* conv_w = (const float*)d_in[1];
    const float* conv_b = (const float*)d_in[2];
    const float* fc1_w  = (const float*)d_in[3];
    const float* fc1_b  = (const float*)d_in[4];
    const float* fc2_w  = (const float*)d_in[5];
    const float* fc2_b  = (const float*)d_in[6];
    float* out = (float*)d_out;

    harris_kernel<<<dim3(7, 7, 32), dim3(32, 32)>>>(x);
    topk_kernel<<<32, 1024>>>();
    patch_conv_kernel<<<NPATCH, 256>>>(x, conv_w, conv_b);
    fc1_kernel<<<dim3(64, 4), 128>>>(fc1_w);
    fc1_finish<<<512, 256>>>(fc1_b);
    fc2_kernel<<<NCLASS / 8, 256>>>(fc2_w, fc2_b, out);
}

// round 2
// speedup vs baseline: 1.9437x; 1.9437x over previous
#include <cuda_runtime.h>
#include <cuda_bf16.h>

#define H_IMG 224
#define W_IMG 224
#define NPIX (H_IMG * W_IMG)          // 50176
#define BATCH 32
#define KKP 64
#define PATCH 16
#define NCLASS 1000
#define NPATCH (BATCH * KKP)          // 2048
#define FEAT 2048                      // 8*16*16
#define FC1OUT 64
#define FC2IN (KKP * FC1OUT)          // 4096
#define NCHUNK 8
#define CHUNK (NPIX / NCHUNK)         // 6272
#define FC1_SPLIT 16
#define FC2_SPLIT 4

// -------------------- device scratch (no allocation allowed) --------------------
__device__ float g_R[BATCH * NPIX];                        // harris response (masked)
__device__ unsigned long long g_cand[BATCH * NCHUNK * KKP]; // per-chunk top-64 candidates
__device__ int   g_kp[BATCH * KKP];                        // flat pixel indices, rank-ordered
__device__ float g_H1[NPATCH * FEAT];                      // conv features
__device__ float g_Cpart[FC1_SPLIT * NPATCH * FC1OUT];     // fc1 split-K partials (8MB)
__device__ float g_H2[NPATCH * FC1OUT];                    // relu(fc1)
__device__ float g_F2p[FC2_SPLIT * BATCH * NCLASS];        // fc2 split-K partials

// ==================== 1. Harris response ====================
__global__ void __launch_bounds__(1024) harris_kernel(const float* __restrict__ x) {
    __shared__ float g[36][37];
    __shared__ float dxs[34][35];
    __shared__ float dys[34][35];

    const int b  = blockIdx.z;
    const int ox0 = blockIdx.x * 32, oy0 = blockIdx.y * 32;
    const int tid = threadIdx.y * 32 + threadIdx.x;
    const float* xb = x + (size_t)b * 3 * NPIX;

    for (int i = tid; i < 36 * 36; i += 1024) {
        int r = i / 36, c = i % 36;
        int yy = oy0 - 2 + r, xx = ox0 - 2 + c;
        float v = 0.0f;
        if (yy >= 0 && yy < H_IMG && xx >= 0 && xx < W_IMG) {
            int off = yy * W_IMG + xx;
            v = (xb[off] + xb[NPIX + off] + xb[2 * NPIX + off]) / 3.0f;
        }
        g[r][c] = v;
    }
    __syncthreads();

    for (int i = tid; i < 34 * 34; i += 1024) {
        int r = i / 34, c = i % 34;
        float lft = g[r][c]     + g[r + 1][c]     + g[r + 2][c];
        float rgt = g[r][c + 2] + g[r + 1][c + 2] + g[r + 2][c + 2];
        float top = g[r][c]     + g[r][c + 1]     + g[r][c + 2];
        float bot = g[r + 2][c] + g[r + 2][c + 1] + g[r + 2][c + 2];
        dxs[r][c] = rgt - lft;
        dys[r][c] = bot - top;
    }
    __syncthreads();

    const int ty = threadIdx.y, tx = threadIdx.x;
    const int oy = oy0 + ty, ox = ox0 + tx;

    const float GW[3][3] = {{0.0625f, 0.125f, 0.0625f},
                            {0.125f,  0.25f,  0.125f},
                            {0.0625f, 0.125f, 0.0625f}};
    float sxx = 0.f, syy = 0.f, sxy = 0.f;
#pragma unroll
    for (int u = 0; u < 3; u++)
#pragma unroll
        for (int v = 0; v < 3; v++) {
            float w = GW[u][v];
            float a = dxs[ty + u][tx + v];
            float d = dys[ty + u][tx + v];
            sxx += w * (a * a);
            syy += w * (d * d);
            sxy += w * (a * d);
        }
    float tr = sxx + syy;
    float R = sxx * syy - sxy * sxy - 0.04f * tr * tr;
    bool inmask = (oy >= PATCH && oy < H_IMG - PATCH && ox >= PATCH && ox < W_IMG - PATCH);
    g_R[(size_t)b * NPIX + oy * W_IMG + ox] = inmask ? R : 0.0f;
}

// ==================== 2. exact top-64: two-stage ====================
__device__ __forceinline__ unsigned int fkey(float f) {
    unsigned int u = __float_as_uint(f);
    return (u & 0x80000000u) ? ~u : (u | 0x80000000u);
}

// Stage 1: per (image, chunk) exact top-64 via radix select in smem.
__global__ void __launch_bounds__(256) topk_stage1() {
    const int c = blockIdx.x;      // chunk 0..7
    const int b = blockIdx.y;      // image
    const int tid = threadIdx.x;
    const int base = c * CHUNK;
    const float* R = g_R + (size_t)b * NPIX + base;

    __shared__ unsigned int keys[CHUNK];
    __shared__ unsigned int hist[256];
    __shared__ unsigned int sh_prefix;
    __shared__ int sh_kneed;
    __shared__ unsigned long long cand[64];
    __shared__ int sh_cnt;
    __shared__ int sh_min;

    for (int i = tid; i < CHUNK; i += 256) keys[i] = fkey(R[i]);
    __syncthreads();

    unsigned int prefix = 0;
    int kneed = KKP;
    for (int level = 0; level < 4; level++) {
        int shift = 24 - 8 * level;
        hist[tid] = 0u;
        __syncthreads();
        for (int i = tid; i < CHUNK; i += 256) {
            unsigned int u = keys[i];
            bool ok = (level == 0) || ((u >> (shift + 8)) == (prefix >> (shift + 8)));
            if (ok) atomicAdd(&hist[(u >> shift) & 0xFFu], 1u);
        }
        __syncthreads();
        if (tid == 0) {
            int cum = 0, d = 255;
            for (; d >= 0; d--) {
                cum += (int)hist[d];
                if (cum >= kneed) break;
            }
            sh_kneed = kneed - (cum - (int)hist[d]);
            sh_prefix = prefix | ((unsigned int)d << shift);
        }
        __syncthreads();
        prefix = sh_prefix;
        kneed = sh_kneed;
        __syncthreads();
    }

    const unsigned int T = prefix;
    const int cGT = KKP - kneed;

    if (tid == 0) sh_cnt = 0;
    __syncthreads();
    for (int i = tid; i < CHUNK; i += 256) {
        unsigned int u = keys[i];
        if (u > T) {
            int pos = atomicAdd(&sh_cnt, 1);
            cand[pos] = (((unsigned long long)(~u)) << 32) | (unsigned long long)(base + i);
        }
    }
    __syncthreads();

    // ties (== T): smallest local indices first
    int last = -1;
    for (int t = 0; t < kneed; t++) {
        if (tid == 0) sh_min = CHUNK;
        __syncthreads();
        for (int i = tid; i < CHUNK; i += 256)
            if (i > last && keys[i] == T) atomicMin(&sh_min, i);
        __syncthreads();
        int found = sh_min;
        if (tid == 0)
            cand[cGT + t] = (((unsigned long long)(~T)) << 32) | (unsigned long long)(base + found);
        last = found;
        __syncthreads();
    }

    if (tid < 64) g_cand[(b * NCHUNK + c) * KKP + tid] = cand[tid];
}

// Stage 2: per image, bitonic-sort 512 candidates, keep top 64 in order.
__global__ void __launch_bounds__(512) topk_stage2() {
    const int b = blockIdx.x;
    const int tid = threadIdx.x;
    __shared__ unsigned long long s[512];
    s[tid] = g_cand[b * 512 + tid];
    __syncthreads();

    for (int ksz = 2; ksz <= 512; ksz <<= 1) {
        for (int j = ksz >> 1; j > 0; j >>= 1) {
            int ixj = tid ^ j;
            if (ixj > tid) {
                bool up = ((tid & ksz) == 0);
                unsigned long long a = s[tid], c = s[ixj];
                if ((a > c) == up) { s[tid] = c; s[ixj] = a; }
            }
            __syncthreads();
        }
    }
    if (tid < KKP) g_kp[b * KKP + tid] = (int)(s[tid] & 0xFFFFFFFFULL);
}

// ==================== 3. patch extraction + conv3x3 + relu ====================
__global__ void __launch_bounds__(256) patch_conv_kernel(const float* __restrict__ x,
                                                         const float* __restrict__ conv_w,
                                                         const float* __restrict__ conv_b) {
    __shared__ float sp[3][16][16];
    __shared__ float sw[8 * 27];
    __shared__ float sb[8];

    const int p  = blockIdx.x;
    const int b  = p >> 6;
    const int kk = p & 63;
    const int tid = threadIdx.x;

    if (tid < 216) sw[tid] = conv_w[tid];
    else if (tid < 224) sb[tid - 216] = conv_b[tid - 216];

    const int idx = g_kp[b * KKP + kk];
    const float rowf = (float)(idx / W_IMG);
    const float colf = (float)(idx % W_IMG);
    float cy = fminf(fmaxf((rowf / 224.0f - 0.5f) * 2.0f, -1.0f), 1.0f);
    float cx = fminf(fmaxf((colf / 224.0f - 0.5f) * 2.0f, -1.0f), 1.0f);
    float y01 = (cy + 1.0f) * 0.5f;
    float x01 = (cx + 1.0f) * 0.5f;

    const float rf = 16.0f / 224.0f;
    const float step = (2.0f * rf) / 15.0f;

    for (int s = tid; s < 768; s += 256) {
        int c = s >> 8;
        int pos = s & 255;
        int i = pos >> 4, j = pos & 15;
        float pgj = (j == 15) ? rf : (-rf + (float)j * step);
        float pgi = (i == 15) ? rf : (-rf + (float)i * step);
        // faithful to reference's swapped broadcast: grid_x uses row(y01), grid_y uses col(x01)
        float gxn = (pgj + y01) * 2.0f - 1.0f;
        float gyn = (pgi + x01) * 2.0f - 1.0f;
        float gx = (gxn + 1.0f) * 0.5f * 223.0f;
        float gy = (gyn + 1.0f) * 0.5f * 223.0f;

        float x0f = floorf(gx), y0f = floorf(gy);
        float wx1 = gx - x0f, wx0 = 1.0f - wx1;
        float wy1 = gy - y0f, wy0 = 1.0f - wy1;
        int x0 = (int)x0f, y0 = (int)y0f;
        int x1 = x0 + 1, y1 = y0 + 1;

        const float* img = x + ((size_t)b * 3 + c) * NPIX;
        auto fetch = [&](int xi, int yi) -> float {
            bool v = (xi >= 0 && xi < W_IMG && yi >= 0 && yi < H_IMG);
            int xc = min(max(xi, 0), W_IMG - 1);
            int yc = min(max(yi, 0), H_IMG - 1);
            float val = img[yc * W_IMG + xc];
            return v ? val : 0.0f;
        };
        float out = fetch(x0, y0) * (wx0 * wy0)
                  + fetch(x1, y0) * (wx1 * wy0)
                  + fetch(x0, y1) * (wx0 * wy1)
                  + fetch(x1, y1) * (wx1 * wy1);
        sp[c][i][j] = out;
    }
    __syncthreads();

    const int i = tid >> 4, j = tid & 15;
    float nb[3][3][3];
#pragma unroll
    for (int ci = 0; ci < 3; ci++)
#pragma unroll
        for (int u = 0; u < 3; u++)
#pragma unroll
            for (int v = 0; v < 3; v++) {
                int iy = i + u - 1, ix = j + v - 1;
                nb[ci][u][v] = (iy >= 0 && iy < 16 && ix >= 0 && ix < 16) ? sp[ci][iy][ix] : 0.0f;
            }

#pragma unroll
    for (int co = 0; co < 8; co++) {
        float acc = sb[co];
#pragma unroll
        for (int ci = 0; ci < 3; ci++)
#pragma unroll
            for (int u = 0; u < 3; u++)
#pragma unroll
                for (int v = 0; v < 3; v++)
                    acc += nb[ci][u][v] * sw[co * 27 + ci * 9 + u * 3 + v];
        g_H1[(size_t)p * FEAT + co * 256 + tid] = fmaxf(acc, 0.0f);
    }
}

// ==================== 4. fc1 GEMM (split-K=16, 64x64 tiles, 4x4/thread) ====================
__global__ void __launch_bounds__(256) fc1_kernel(const float* __restrict__ fc1_w) {
    __shared__ float As[32][68];   // [k][m], 68-float stride (odd # of float4 -> conflict-free)
    __shared__ float Bs[32][68];   // [k][n]

    const int p0 = blockIdx.x * 64;
    const int k0 = blockIdx.y * 128;
    const int t = threadIdx.x;
    const int tm4 = (t >> 4) * 4;   // 0..60
    const int tn4 = (t & 15) * 4;   // 0..60

    float acc[4][4];
#pragma unroll
    for (int m = 0; m < 4; m++)
#pragma unroll
        for (int n = 0; n < 4; n++) acc[m][n] = 0.0f;

    for (int kc = 0; kc < 128; kc += 32) {
#pragma unroll
        for (int r = 0; r < 2; r++) {
            int q = t + r * 256;            // 0..511 -> 512 float4s
            int m = q >> 3;                  // 0..63
            int kq = (q & 7) * 4;            // 0,4,..28
            float4 va = *(const float4*)&g_H1[(size_t)(p0 + m) * FEAT + k0 + kc + kq];
            As[kq][m] = va.x; As[kq + 1][m] = va.y; As[kq + 2][m] = va.z; As[kq + 3][m] = va.w;
            float4 vb = *(const float4*)&fc1_w[(size_t)m * FEAT + k0 + kc + kq];
            Bs[kq][m] = vb.x; Bs[kq + 1][m] = vb.y; Bs[kq + 2][m] = vb.z; Bs[kq + 3][m] = vb.w;
        }
        __syncthreads();
#pragma unroll
        for (int k = 0; k < 32; k++) {
            float4 a = *(const float4*)&As[k][tm4];
            float4 b = *(const float4*)&Bs[k][tn4];
            acc[0][0] = fmaf(a.x, b.x, acc[0][0]); acc[0][1] = fmaf(a.x, b.y, acc[0][1]);
            acc[0][2] = fmaf(a.x, b.z, acc[0][2]); acc[0][3] = fmaf(a.x, b.w, acc[0][3]);
            acc[1][0] = fmaf(a.y, b.x, acc[1][0]); acc[1][1] = fmaf(a.y, b.y, acc[1][1]);
            acc[1][2] = fmaf(a.y, b.z, acc[1][2]); acc[1][3] = fmaf(a.y, b.w, acc[1][3]);
            acc[2][0] = fmaf(a.z, b.x, acc[2][0]); acc[2][1] = fmaf(a.z, b.y, acc[2][1]);
            acc[2][2] = fmaf(a.z, b.z, acc[2][2]); acc[2][3] = fmaf(a.z, b.w, acc[2][3]);
            acc[3][0] = fmaf(a.w, b.x, acc[3][0]); acc[3][1] = fmaf(a.w, b.y, acc[3][1]);
            acc[3][2] = fmaf(a.w, b.z, acc[3][2]); acc[3][3] = fmaf(a.w, b.w, acc[3][3]);
        }
        __syncthreads();
    }

    float* Cp = g_Cpart + (size_t)blockIdx.y * (NPATCH * FC1OUT);
#pragma unroll
    for (int m = 0; m < 4; m++) {
        float4 v = make_float4(acc[m][0], acc[m][1], acc[m][2], acc[m][3]);
        *(float4*)&Cp[(size_t)(p0 + tm4 + m) * FC1OUT + tn4] = v;
    }
}

__global__ void __launch_bounds__(256) fc1_finish(const float* __restrict__ fc1_b) {
    int idx = blockIdx.x * 256 + threadIdx.x;   // < 131072
    int o = idx & 63;
    float v = fc1_b[o];
#pragma unroll
    for (int s = 0; s < FC1_SPLIT; s++)
        v += g_Cpart[(size_t)s * (NPATCH * FC1OUT) + idx];
    g_H2[idx] = fmaxf(v, 0.0f);
}

// ==================== 5. fc2 GEMM (split-K=4) ====================
__global__ void __launch_bounds__(256) fc2_kernel(const float* __restrict__ w2) {
    __shared__ float sH[32][132];   // 132 floats = 33 float4s (odd) -> conflict-free
    __shared__ float sW[8][132];

    const int n0 = blockIdx.x * 8;
    const int kb = blockIdx.y * (FC2IN / FC2_SPLIT);   // 1024-slice
    const int tid = threadIdx.x;
    const int warp = tid >> 5, lane = tid & 31;

    float acc = 0.0f;
    for (int kc = 0; kc < FC2IN / FC2_SPLIT; kc += 128) {
#pragma unroll
        for (int r = 0; r < 4; r++) {
            int q = tid + r * 256;              // 0..1023 float4s
            int bb = q >> 5, kk4 = (q & 31) * 4;
            *(float4*)&sH[bb][kk4] = *(const float4*)&g_H2[(size_t)bb * FC2IN + kb + kc + kk4];
        }
        {
            int oo = tid >> 5, kk4 = (tid & 31) * 4;
            *(float4*)&sW[oo][kk4] = *(const float4*)&w2[(size_t)(n0 + oo) * FC2IN + kb + kc + kk4];
        }
        __syncthreads();
#pragma unroll
        for (int kk = 0; kk < 128; kk += 4) {
            float4 h = *(const float4*)&sH[lane][kk];
            float4 w = *(const float4*)&sW[warp][kk];
            acc = fmaf(h.x, w.x, acc);
            acc = fmaf(h.y, w.y, acc);
            acc = fmaf(h.z, w.z, acc);
            acc = fmaf(h.w, w.w, acc);
        }
        __syncthreads();
    }
    g_F2p[(size_t)blockIdx.y * (BATCH * NCLASS) + lane * NCLASS + n0 + warp] = acc;
}

__global__ void __launch_bounds__(256) fc2_finish(const float* __restrict__ b2,
                                                  float* __restrict__ out) {
    int idx = blockIdx.x * 256 + threadIdx.x;
    if (idx >= BATCH * NCLASS) return;
    int n = idx % NCLASS;
    float v = b2[n];
#pragma unroll
    for (int s = 0; s < FC2_SPLIT; s++)
        v += g_F2p[(size_t)s * (BATCH * NCLASS) + idx];
    out[idx] = v;
}

// ==================== launch ====================
extern "C" void kernel_launch(void* const* d_in, const int* in_sizes, int n_in,
                              void* d_out, int out_size) {
    const float* x      = (const float*)d_in[0];
    const float* conv_w = (const float*)d_in[1];
    const float* conv_b = (const float*)d_in[2];
    const float* fc1_w  = (const float*)d_in[3];
    const float* fc1_b  = (const float*)d_in[4];
    const float* fc2_w  = (const float*)d_in[5];
    const float* fc2_b  = (const float*)d_in[6];
    float* out = (float*)d_out;

    harris_kernel<<<dim3(7, 7, 32), dim3(32, 32)>>>(x);
    topk_stage1<<<dim3(NCHUNK, BATCH), 256>>>();
    topk_stage2<<<BATCH, 512>>>();
    patch_conv_kernel<<<NPATCH, 256>>>(x, conv_w, conv_b);
    fc1_kernel<<<dim3(32, FC1_SPLIT), 256>>>(fc1_w);
    fc1_finish<<<512, 256>>>(fc1_b);
    fc2_kernel<<<dim3(NCLASS / 8, FC2_SPLIT), 256>>>(fc2_w);
    fc2_finish<<<(BATCH * NCLASS + 255) / 256, 256>>>(fc2_b, out);
}